// round 11
// baseline (speedup 1.0000x reference)
#include <cuda_runtime.h>

// Chunk-local reverse inclusive cumsum with scale fusion.
//   g: [B, T, H] f32, BT=64 chunks along T, H=64.
//   out[b, c, t, h] = SCALE * sum_{s >= t} g[b, c, s, h]
//
// R10: high-occupancy variant of the R6 structure. Each thread owns a
// (chunk, quad-column) segment of only 4 rows (16 data regs), SEGS=16
// segments per chunk scanned across lanes at stride 2. __launch_bounds__
// (256, 8) caps regs at 32 -> 8 CTAs/SM -> ~85-100% occupancy (vs 62% at
// RPS=8/40 regs). Total LDG.128/STG.128 instruction count and L1tex
// wavefront count are IDENTICAL to R6; only warp-level parallelism is
// doubled (2x warps at half the per-thread MLP). Streaming __ldcs/__stcs.
//
// Warp layout: lane = seg*2 + c, c in {0,1}: lane pairs are 32B
// contiguous; one warp covers 2 quad-columns over the whole chunk.

static constexpr int BT = 64;
static constexpr int H  = 64;
static constexpr int HQ = H / 4;          // 16 float4 columns per row
static constexpr int SEGS = 16;           // t-segments per chunk
static constexpr int RPS  = BT / SEGS;    // rows per segment = 4
static constexpr float SCALE = 0.5f;

__global__ __launch_bounds__(256, 8)
void rev_cumsum_kernel(const float4* __restrict__ g,
                       float4* __restrict__ out,
                       int n_threads)
{
    int tid = blockIdx.x * blockDim.x + threadIdx.x;
    if (tid >= n_threads) return;

    int c     = tid & 1;                  // quad within pair
    int seg   = (tid >> 1) & (SEGS - 1);  // t-segment 0..15
    int wq    = (tid >> 5) & 7;           // quad-pair group 0..7
    int chunk = tid >> 8;                 // global chunk index

    size_t base = (size_t)chunk * (BT * HQ) + (size_t)(wq * 2 + c);
    const float4* __restrict__ gp = g   + base;
    float4*       __restrict__ op = out + base;

    int row0 = seg * RPS;

    // Load the whole segment: 4 independent streaming LDG.128s, all live
    // until the totals are computed -> MLP=4 per thread, 2x warps vs R6.
    float4 v[RPS];
    #pragma unroll
    for (int j = 0; j < RPS; ++j)
        v[j] = __ldcs(&gp[(row0 + j) * HQ]);

    // Segment totals.
    float tx = 0.f, ty = 0.f, tz = 0.f, tw = 0.f;
    #pragma unroll
    for (int j = 0; j < RPS; ++j) {
        tx += v[j].x; ty += v[j].y; tz += v[j].z; tw += v[j].w;
    }

    // Exclusive suffix-scan of totals across the 16 segments (lane stride 2).
    float cx = __shfl_down_sync(0xffffffffu, tx, 2);
    float cy = __shfl_down_sync(0xffffffffu, ty, 2);
    float cz = __shfl_down_sync(0xffffffffu, tz, 2);
    float cw = __shfl_down_sync(0xffffffffu, tw, 2);
    if (seg == SEGS - 1) { cx = 0.f; cy = 0.f; cz = 0.f; cw = 0.f; }
    #pragma unroll
    for (int d = 1; d < SEGS; d <<= 1) {
        float ax = __shfl_down_sync(0xffffffffu, cx, 2 * d);
        float ay = __shfl_down_sync(0xffffffffu, cy, 2 * d);
        float az = __shfl_down_sync(0xffffffffu, cz, 2 * d);
        float aw = __shfl_down_sync(0xffffffffu, cw, 2 * d);
        if (seg + d < SEGS) { cx += ax; cy += ay; cz += az; cw += aw; }
    }
    // cx.. = sum of totals of all segments strictly after this one.

    // Reverse inclusive cumsum within the segment, seeded with the carry;
    // streaming stores (evict-first).
    float rx = cx, ry = cy, rz = cz, rw = cw;
    #pragma unroll
    for (int j = RPS - 1; j >= 0; --j) {
        rx += v[j].x; ry += v[j].y; rz += v[j].z; rw += v[j].w;
        float4 o;
        o.x = rx * SCALE; o.y = ry * SCALE; o.z = rz * SCALE; o.w = rw * SCALE;
        __stcs(&op[(row0 + j) * HQ], o);
    }
}

extern "C" void kernel_launch(void* const* d_in, const int* in_sizes, int n_in,
                              void* d_out, int out_size)
{
    const float4* g   = (const float4*)d_in[0];
    float4*       out = (float4*)d_out;

    int total_elems = in_sizes[0];                 // B * T * H
    int chunks    = total_elems / (BT * H);        // 4096
    int n_threads = chunks * (SEGS * HQ);          // 256 threads per chunk

    int threads = 256;
    int blocks  = (n_threads + threads - 1) / threads;
    rev_cumsum_kernel<<<blocks, threads>>>(g, out, n_threads);
}

// round 12
// speedup vs baseline: 1.1986x; 1.1986x over previous
#include <cuda_runtime.h>

// Chunk-local reverse inclusive cumsum with scale fusion.
//   g: [B, T, H] f32, BT=64 chunks along T, H=64.
//   out[b, c, t, h] = SCALE * sum_{s >= t} g[b, c, s, h]
//
// FINAL — R6 configuration, the Pareto optimum verified across R2-R11:
//   - 8 threads per (chunk, quad-column), each owning 8 rows at float4 width
//   - lane = seg*4 + c: 64B-contiguous lane groups -> 8 L1 lines per LDG.128
//     (R10's stride-2 layout doubled wavefronts -> L1tex-bound, +33% time)
//   - 524288 threads -> ~62% occupancy (6 CTAs/SM at 40 regs); pushing
//     occupancy higher (R10: 86%) or lower (R7: 40%) both regressed
//   - 8 independent LDG.128s live until the segment total -> MLP=8
//   - segment totals suffix-scanned across lanes via shuffles (no smem)
//   - streaming cache hints (__ldcs/__stcs)
//
// Design space fully mapped: scalar (LSU-bound 19.1), RPS=4 (wavefront-
// bound 25.8), persistent (reg/occ-bound 21.4), RPS=8 (18.85-19.5, best).
// ~134.2 MB compulsory traffic at ~7 TB/s combined L2 throughput; no
// remaining lever moves the plateau.

static constexpr int BT = 64;
static constexpr int H  = 64;
static constexpr int HQ = H / 4;          // 16 float4 columns per row
static constexpr int SEGS = 8;            // t-segments per chunk
static constexpr int RPS  = BT / SEGS;    // rows per segment = 8
static constexpr float SCALE = 0.5f;

__global__ __launch_bounds__(256)
void rev_cumsum_kernel(const float4* __restrict__ g,
                       float4* __restrict__ out,
                       int n_threads)
{
    int tid = blockIdx.x * blockDim.x + threadIdx.x;
    if (tid >= n_threads) return;

    int c     = tid & 3;                  // quad within group of 4
    int seg   = (tid >> 2) & (SEGS - 1);  // t-segment 0..7
    int wq    = (tid >> 5) & 3;           // quad-group 0..3
    int chunk = tid >> 7;                 // global chunk index

    size_t base = (size_t)chunk * (BT * HQ) + (size_t)(wq * 4 + c);
    const float4* __restrict__ gp = g   + base;
    float4*       __restrict__ op = out + base;

    int row0 = seg * RPS;

    // Load the whole segment: 8 independent streaming LDG.128s, all live
    // until the totals are computed -> guaranteed MLP=8.
    float4 v[RPS];
    #pragma unroll
    for (int j = 0; j < RPS; ++j)
        v[j] = __ldcs(&gp[(row0 + j) * HQ]);

    // Segment totals.
    float tx = 0.f, ty = 0.f, tz = 0.f, tw = 0.f;
    #pragma unroll
    for (int j = 0; j < RPS; ++j) {
        tx += v[j].x; ty += v[j].y; tz += v[j].z; tw += v[j].w;
    }

    // Exclusive suffix-scan of totals across segments (same c, lane stride 4).
    float cx = __shfl_down_sync(0xffffffffu, tx, 4);
    float cy = __shfl_down_sync(0xffffffffu, ty, 4);
    float cz = __shfl_down_sync(0xffffffffu, tz, 4);
    float cw = __shfl_down_sync(0xffffffffu, tw, 4);
    if (seg == SEGS - 1) { cx = 0.f; cy = 0.f; cz = 0.f; cw = 0.f; }
    #pragma unroll
    for (int d = 1; d < SEGS; d <<= 1) {
        float ax = __shfl_down_sync(0xffffffffu, cx, 4 * d);
        float ay = __shfl_down_sync(0xffffffffu, cy, 4 * d);
        float az = __shfl_down_sync(0xffffffffu, cz, 4 * d);
        float aw = __shfl_down_sync(0xffffffffu, cw, 4 * d);
        if (seg + d < SEGS) { cx += ax; cy += ay; cz += az; cw += aw; }
    }
    // cx.. = sum of totals of all segments strictly after this one.

    // Reverse inclusive cumsum within the segment, seeded with the carry;
    // streaming stores (evict-first).
    float rx = cx, ry = cy, rz = cz, rw = cw;
    #pragma unroll
    for (int j = RPS - 1; j >= 0; --j) {
        rx += v[j].x; ry += v[j].y; rz += v[j].z; rw += v[j].w;
        float4 o;
        o.x = rx * SCALE; o.y = ry * SCALE; o.z = rz * SCALE; o.w = rw * SCALE;
        __stcs(&op[(row0 + j) * HQ], o);
    }
}

extern "C" void kernel_launch(void* const* d_in, const int* in_sizes, int n_in,
                              void* d_out, int out_size)
{
    const float4* g   = (const float4*)d_in[0];
    float4*       out = (float4*)d_out;

    int total_elems = in_sizes[0];                 // B * T * H
    int chunks    = total_elems / (BT * H);        // 4096
    int n_threads = chunks * (SEGS * HQ);          // 128 threads per chunk

    int threads = 256;
    int blocks  = (n_threads + threads - 1) / threads;
    rev_cumsum_kernel<<<blocks, threads>>>(g, out, n_threads);
}

// round 13
// speedup vs baseline: 1.2582x; 1.0496x over previous
#include <cuda_runtime.h>

// Chunk-local reverse inclusive cumsum with scale fusion.
//   g: [B, T, H] f32, BT=64 chunks along T, H=64.
//   out[b, c, t, h] = SCALE * sum_{s >= t} g[b, c, s, h]
//
// R12: full-line wavefront variant. Keeps R6's MLP=8 / 128-bit ops / 40ish
// regs, but lane groups are 8 quads = 128B = ONE full L1 line per
// seg-group: 4 wavefronts per LDG.128/STG.128 instead of R6's 8. The
// 8-segment suffix scan now spans a warp PAIR (seg = seg_hi*4 + seg_lo);
// the cross-warp carry moves through 128B of smem + one __syncthreads.
//
// Thread layout (128 threads per chunk):
//   c      = tid & 7          quad within half-row (8 quads = 128B line)
//   seg_lo = (tid >> 3) & 3   segment within warp
//   seg_hi = (tid >> 5) & 1   warp parity: segs 0-3 vs 4-7
//   half   = (tid >> 6) & 1   which 8-quad half of the 16-quad row
//   chunk  = tid >> 7

static constexpr int BT = 64;
static constexpr int H  = 64;
static constexpr int HQ = H / 4;          // 16 float4 columns per row
static constexpr int SEGS = 8;            // t-segments per chunk
static constexpr int RPS  = BT / SEGS;    // rows per segment = 8
static constexpr float SCALE = 0.5f;

__global__ __launch_bounds__(256)
void rev_cumsum_kernel(const float4* __restrict__ g,
                       float4* __restrict__ out)
{
    // carry_sm[chunk_in_block][half][c] : upper-warp inclusive suffix total
    __shared__ float4 carry_sm[2][2][8];

    int tid = blockIdx.x * blockDim.x + threadIdx.x;  // grid is exact

    int c      = tid & 7;
    int seg_lo = (tid >> 3) & 3;
    int seg_hi = (tid >> 5) & 1;
    int half   = (tid >> 6) & 1;
    int chunk  = tid >> 7;
    int cib    = (threadIdx.x >> 7) & 1;  // chunk-in-block

    int seg  = seg_hi * 4 + seg_lo;
    int row0 = seg * RPS;

    size_t base = (size_t)chunk * (BT * HQ) + (size_t)(half * 8 + c);
    const float4* __restrict__ gp = g   + base;
    float4*       __restrict__ op = out + base;

    // 8 independent streaming LDG.128s, all live until totals -> MLP=8.
    // Per LDG: 4 seg_lo groups x 8 lanes x 16B = 4 full 128B lines.
    float4 v[RPS];
    #pragma unroll
    for (int j = 0; j < RPS; ++j)
        v[j] = __ldcs(&gp[(row0 + j) * HQ]);

    // Segment totals.
    float tx = 0.f, ty = 0.f, tz = 0.f, tw = 0.f;
    #pragma unroll
    for (int j = 0; j < RPS; ++j) {
        tx += v[j].x; ty += v[j].y; tz += v[j].z; tw += v[j].w;
    }

    // Warp-local exclusive suffix scan over the 4 local segments
    // (lane stride 8 along seg_lo).
    float cx = __shfl_down_sync(0xffffffffu, tx, 8);
    float cy = __shfl_down_sync(0xffffffffu, ty, 8);
    float cz = __shfl_down_sync(0xffffffffu, tz, 8);
    float cw = __shfl_down_sync(0xffffffffu, tw, 8);
    if (seg_lo == 3) { cx = 0.f; cy = 0.f; cz = 0.f; cw = 0.f; }
    #pragma unroll
    for (int d = 1; d < 4; d <<= 1) {
        float ax = __shfl_down_sync(0xffffffffu, cx, 8 * d);
        float ay = __shfl_down_sync(0xffffffffu, cy, 8 * d);
        float az = __shfl_down_sync(0xffffffffu, cz, 8 * d);
        float aw = __shfl_down_sync(0xffffffffu, cw, 8 * d);
        if (seg_lo + d < 4) { cx += ax; cy += ay; cz += az; cw += aw; }
    }
    // cx.. = exclusive suffix over this warp's local segments.

    // Cross-warp carry: upper warp (segs 4-7) publishes its inclusive
    // suffix total (= cx + tx at seg_lo==0); lower warp adds it.
    if (seg_hi == 1 && seg_lo == 0)
        carry_sm[cib][half][c] = make_float4(cx + tx, cy + ty, cz + tz, cw + tw);
    __syncthreads();
    if (seg_hi == 0) {
        float4 e = carry_sm[cib][half][c];
        cx += e.x; cy += e.y; cz += e.z; cw += e.w;
    }

    // Reverse inclusive cumsum within the segment, seeded with the carry;
    // streaming stores (4 full lines per STG.128).
    float rx = cx, ry = cy, rz = cz, rw = cw;
    #pragma unroll
    for (int j = RPS - 1; j >= 0; --j) {
        rx += v[j].x; ry += v[j].y; rz += v[j].z; rw += v[j].w;
        float4 o;
        o.x = rx * SCALE; o.y = ry * SCALE; o.z = rz * SCALE; o.w = rw * SCALE;
        __stcs(&op[(row0 + j) * HQ], o);
    }
}

extern "C" void kernel_launch(void* const* d_in, const int* in_sizes, int n_in,
                              void* d_out, int out_size)
{
    const float4* g   = (const float4*)d_in[0];
    float4*       out = (float4*)d_out;

    int total_elems = in_sizes[0];                 // B * T * H
    int chunks    = total_elems / (BT * H);        // 4096
    int n_threads = chunks * (SEGS * HQ);          // 128 threads per chunk
    int threads = 256;
    int blocks  = n_threads / threads;             // exact: 524288/256 = 2048
    rev_cumsum_kernel<<<blocks, threads>>>(g, out);
}